// round 15
// baseline (speedup 1.0000x reference)
#include <cuda_runtime.h>
#include <cuda_bf16.h>
#include <cstdint>
#include <math.h>

// ---------------- problem constants ----------------
#define B_   2
#define S_   2048
#define H_   2048
#define HQ_  32
#define HK_  8
#define D_   64
#define M_   (B_ * S_)        // 4096 rows

// ---------------- device scratch ----------------
__device__ float g_rope[S_ * D_];

__device__ __nv_bfloat16 g_Xh[(size_t)M_ * H_];
__device__ __nv_bfloat16 g_Xl[(size_t)M_ * H_];
__device__ __nv_bfloat16 g_Wqh[(size_t)H_ * H_];
__device__ __nv_bfloat16 g_Wql[(size_t)H_ * H_];
__device__ __nv_bfloat16 g_Wkh[(size_t)(HK_*D_) * H_];
__device__ __nv_bfloat16 g_Wkl[(size_t)(HK_*D_) * H_];
__device__ __nv_bfloat16 g_Wvh[(size_t)(HK_*D_) * H_];
__device__ __nv_bfloat16 g_Wvl[(size_t)(HK_*D_) * H_];
__device__ __nv_bfloat16 g_Woh[(size_t)H_ * H_];
__device__ __nv_bfloat16 g_Wol[(size_t)H_ * H_];

__device__ __nv_bfloat16 g_qh[(size_t)M_ * HQ_ * D_];
__device__ __nv_bfloat16 g_ql[(size_t)M_ * HQ_ * D_];
__device__ __nv_bfloat16 g_kh[(size_t)M_ * HK_ * D_];
__device__ __nv_bfloat16 g_kl[(size_t)M_ * HK_ * D_];
__device__ __nv_bfloat16 g_vh[(size_t)M_ * HK_ * D_];
__device__ __nv_bfloat16 g_vl[(size_t)M_ * HK_ * D_];
__device__ __nv_bfloat16 g_Ch[(size_t)M_ * H_];
__device__ __nv_bfloat16 g_Cl[(size_t)M_ * H_];

// ---------------- helpers ----------------
__device__ __forceinline__ uint32_t smem_u32(const void* p) {
    uint32_t a;
    asm("{ .reg .u64 t; cvta.to.shared.u64 t, %1; cvt.u32.u64 %0, t; }" : "=r"(a) : "l"(p));
    return a;
}

__device__ __forceinline__ void ldm_x4(uint32_t r[4], uint32_t addr) {
    asm volatile("ldmatrix.sync.aligned.m8n8.x4.shared.b16 {%0,%1,%2,%3}, [%4];"
        : "=r"(r[0]), "=r"(r[1]), "=r"(r[2]), "=r"(r[3]) : "r"(addr));
}
__device__ __forceinline__ void ldm_x4_t(uint32_t r[4], uint32_t addr) {
    asm volatile("ldmatrix.sync.aligned.m8n8.x4.trans.shared.b16 {%0,%1,%2,%3}, [%4];"
        : "=r"(r[0]), "=r"(r[1]), "=r"(r[2]), "=r"(r[3]) : "r"(addr));
}

__device__ __forceinline__ void mma16816(float c[4], const uint32_t a[4],
                                         uint32_t b0, uint32_t b1) {
    asm volatile(
        "mma.sync.aligned.m16n8k16.row.col.f32.bf16.bf16.f32 "
        "{%0,%1,%2,%3},{%4,%5,%6,%7},{%8,%9},{%0,%1,%2,%3};"
        : "+f"(c[0]), "+f"(c[1]), "+f"(c[2]), "+f"(c[3])
        : "r"(a[0]), "r"(a[1]), "r"(a[2]), "r"(a[3]), "r"(b0), "r"(b1));
}

__device__ __forceinline__ uint32_t pack2_hi(float a, float b) {
    __nv_bfloat162 t = __floats2bfloat162_rn(a, b);
    return *(uint32_t*)&t;
}
__device__ __forceinline__ uint32_t pack2_lo(float a, float b) {
    __nv_bfloat16 ah = __float2bfloat16_rn(a);
    __nv_bfloat16 bh = __float2bfloat16_rn(b);
    __nv_bfloat162 t = __floats2bfloat162_rn(a - __bfloat162float(ah),
                                             b - __bfloat162float(bh));
    return *(uint32_t*)&t;
}

// ---------------- fused split of all 5 inputs (fp32 -> bf16 hi/lo) ---------
#define N4_X   (M_ * H_ / 4)
#define N4_WQ  (H_ * H_ / 4)
#define N4_WK  (HK_ * D_ * H_ / 4)
#define N4_WV  (HK_ * D_ * H_ / 4)
#define N4_WO  (H_ * H_ / 4)
#define N4_ALL (N4_X + N4_WQ + N4_WK + N4_WV + N4_WO)

__global__ __launch_bounds__(256) void split_all_kernel(
    const float* __restrict__ X,  const float* __restrict__ Wq,
    const float* __restrict__ Wk, const float* __restrict__ Wv,
    const float* __restrict__ Wo,
    __nv_bfloat16* __restrict__ Xh,  __nv_bfloat16* __restrict__ Xl,
    __nv_bfloat16* __restrict__ Wqh, __nv_bfloat16* __restrict__ Wql,
    __nv_bfloat16* __restrict__ Wkh, __nv_bfloat16* __restrict__ Wkl,
    __nv_bfloat16* __restrict__ Wvh, __nv_bfloat16* __restrict__ Wvl,
    __nv_bfloat16* __restrict__ Woh, __nv_bfloat16* __restrict__ Wol)
{
    int i = blockIdx.x * blockDim.x + threadIdx.x;
    if (i >= N4_ALL) return;
    const float* in;
    __nv_bfloat16 *hi, *lo;
    if (i < N4_X)                          { in = X;  hi = Xh;  lo = Xl; }
    else if ((i -= N4_X)  < N4_WQ)         { in = Wq; hi = Wqh; lo = Wql; }
    else if ((i -= N4_WQ) < N4_WK)         { in = Wk; hi = Wkh; lo = Wkl; }
    else if ((i -= N4_WK) < N4_WV)         { in = Wv; hi = Wvh; lo = Wvl; }
    else      { i -= N4_WV;                  in = Wo; hi = Woh; lo = Wol; }

    float4 x = *(const float4*)(in + (size_t)i * 4);
    __nv_bfloat16 h[4], l[4];
    float xs[4] = {x.x, x.y, x.z, x.w};
#pragma unroll
    for (int j = 0; j < 4; j++) {
        h[j] = __float2bfloat16_rn(xs[j]);
        l[j] = __float2bfloat16_rn(xs[j] - __bfloat162float(h[j]));
    }
    *(uint2*)(hi + (size_t)i * 4) = *(uint2*)h;
    *(uint2*)(lo + (size_t)i * 4) = *(uint2*)l;
}

// ---------------- RoPE table (double precision, separate kernel) -----------
__global__ void rope_table_kernel(float* __restrict__ tab)
{
    int idx = blockIdx.x * blockDim.x + threadIdx.x;
    if (idx >= S_ * 32) return;
    int half = idx & 31;
    int pos  = idx >> 5;
    double inv = pow(10000.0, -((double)(2 * half)) / 64.0);
    double ang = (double)pos * inv;
    tab[pos * 64 + half]      = (float)cos(ang);
    tab[pos * 64 + 32 + half] = (float)sin(ang);
}

// ---------------- bf16x3 GEMM mainloop: BK=32, 2 stages, 1 sync/chunk ------
// 128x128 block tile, 256 threads (8 warps, 2x4), warp tile 64x32.
// R9-proven structure. 80 KB smem + <=128 regs -> 2 CTAs/SM (load-bearing).
#define GP2   80
#define TIL2  (128 * GP2)          // 10240
#define STG2  (4 * TIL2)           // 40960
#define GSM2  (2 * STG2)           // 81920

__device__ __forceinline__ void gemm_mainloop(
    const __nv_bfloat16* __restrict__ Ah, const __nv_bfloat16* __restrict__ Al,
    const __nv_bfloat16* __restrict__ Bh, const __nv_bfloat16* __restrict__ Bl,
    int K, int bm, int bn, char* smp, float c[4][4][4])
{
    const uint32_t sb = smem_u32(smp);
    const int tid  = threadIdx.x;
    const int wid  = tid >> 5;
    const int lane = tid & 31;
    const int wm = (wid & 1) * 64;
    const int wn = (wid >> 1) * 32;

    const __nv_bfloat16* gp[4] = {
        Ah + (size_t)bm * K, Al + (size_t)bm * K,
        Bh + (size_t)bn * K, Bl + (size_t)bn * K };

    const uint32_t a_off = (uint32_t)(lane & 15) * GP2 + (uint32_t)(lane >> 4) * 16;
    const uint32_t b_off = (uint32_t)((lane & 7) + ((lane & 16) >> 1)) * GP2
                         + (uint32_t)((lane >> 3) & 1) * 16;

#pragma unroll
    for (int i = 0; i < 4; i++)
#pragma unroll
        for (int j = 0; j < 4; j++)
#pragma unroll
            for (int q = 0; q < 4; q++) c[i][j][q] = 0.0f;

    const int nc = K >> 5;

    auto load_stage = [&](int stage, int k0) {
        const uint32_t sbase = sb + (uint32_t)stage * STG2;
#pragma unroll
        for (int rep = 0; rep < 2; rep++) {
            int idx = rep * 256 + tid;
            int row = idx >> 2, ch = idx & 3;
            uint32_t so = (uint32_t)row * GP2 + (uint32_t)ch * 16;
#pragma unroll
            for (int t = 0; t < 4; t++) {
                const void* src = gp[t] + (size_t)row * K + k0 + ch * 8;
                asm volatile("cp.async.cg.shared.global [%0], [%1], 16;"
                    :: "r"(sbase + (uint32_t)t * TIL2 + so), "l"(src));
            }
        }
        asm volatile("cp.async.commit_group;");
    };

    load_stage(0, 0);

    for (int cidx = 0; cidx < nc; cidx++) {
        asm volatile("cp.async.wait_group 0;" ::: "memory");
        __syncthreads();
        if (cidx + 1 < nc) load_stage((cidx + 1) & 1, (cidx + 1) << 5);

        const uint32_t st = sb + (uint32_t)(cidx & 1) * STG2;
        const uint32_t baseAh = st + 0 * TIL2;
        const uint32_t baseAl = st + 1 * TIL2;
        const uint32_t baseBh = st + 2 * TIL2;
        const uint32_t baseBl = st + 3 * TIL2;

#pragma unroll
        for (int kc = 0; kc < 2; kc++) {
            uint32_t ah[4][4], al[4][4], bh[2][4], bl[2][4];
#pragma unroll
            for (int mt = 0; mt < 4; mt++) {
                uint32_t ro = (uint32_t)(wm + mt * 16) * GP2 + kc * 32;
                ldm_x4(ah[mt], baseAh + ro + a_off);
                ldm_x4(al[mt], baseAl + ro + a_off);
            }
#pragma unroll
            for (int nt = 0; nt < 2; nt++) {
                uint32_t ro = (uint32_t)(wn + nt * 16) * GP2 + kc * 32;
                ldm_x4(bh[nt], baseBh + ro + b_off);
                ldm_x4(bl[nt], baseBl + ro + b_off);
            }
#pragma unroll
            for (int mi = 0; mi < 4; mi++) {
#pragma unroll
                for (int ni = 0; ni < 4; ni++) {
                    const int nt = ni >> 1, hf = (ni & 1) * 2;
                    mma16816(c[mi][ni], ah[mi], bh[nt][hf], bh[nt][hf + 1]);
                    mma16816(c[mi][ni], ah[mi], bl[nt][hf], bl[nt][hf + 1]);
                    mma16816(c[mi][ni], al[mi], bh[nt][hf], bh[nt][hf + 1]);
                }
            }
        }
    }
}

// fused QKV projection + RoPE + bf16 hi/lo split.
// blockIdx.x 0..15 -> Q, 16..19 -> K, 20..23 -> V
#define SPITCH 132   // fp32 staging pitch (floats)

__global__ __launch_bounds__(256, 2) void gemm_qkv(
    const __nv_bfloat16* __restrict__ Xh, const __nv_bfloat16* __restrict__ Xl,
    const __nv_bfloat16* __restrict__ Wqh, const __nv_bfloat16* __restrict__ Wql,
    const __nv_bfloat16* __restrict__ Wkh, const __nv_bfloat16* __restrict__ Wkl,
    const __nv_bfloat16* __restrict__ Wvh, const __nv_bfloat16* __restrict__ Wvl,
    const float* __restrict__ tab,
    __nv_bfloat16* __restrict__ qh, __nv_bfloat16* __restrict__ ql,
    __nv_bfloat16* __restrict__ kh, __nv_bfloat16* __restrict__ kl,
    __nv_bfloat16* __restrict__ vh, __nv_bfloat16* __restrict__ vl)
{
    extern __shared__ char sm[];
    const int nb = blockIdx.x;
    const int bm = blockIdx.y * 128;

    const __nv_bfloat16 *Bh, *Bl;
    __nv_bfloat16 *oh, *ol;
    int N, bn;
    bool dorope;
    float scale;
    if (nb < 16)      { Bh = Wqh; Bl = Wql; oh = qh; ol = ql; N = HQ_ * D_; bn = nb * 128;        dorope = true;  scale = 0.125f; }
    else if (nb < 20) { Bh = Wkh; Bl = Wkl; oh = kh; ol = kl; N = HK_ * D_; bn = (nb - 16) * 128; dorope = true;  scale = 1.0f; }
    else              { Bh = Wvh; Bl = Wvl; oh = vh; ol = vl; N = HK_ * D_; bn = (nb - 20) * 128; dorope = false; scale = 1.0f; }

    float c[4][4][4];
    gemm_mainloop(Xh, Xl, Bh, Bl, H_, bm, bn, sm, c);

    // ---- stage fp32 tile in smem ----
    float* st = (float*)sm;
    const int tid  = threadIdx.x;
    const int wid  = tid >> 5;
    const int lane = tid & 31;
    const int wm = (wid & 1) * 64;
    const int wn = (wid >> 1) * 32;
    const int g  = lane >> 2;
    const int tq = lane & 3;

    __syncthreads();
#pragma unroll
    for (int mi = 0; mi < 4; mi++) {
#pragma unroll
        for (int ni = 0; ni < 4; ni++) {
            int r0 = wm + mi * 16 + g;
            int cc = wn + ni * 8 + tq * 2;
            *(float2*)&st[r0 * SPITCH + cc]       = make_float2(c[mi][ni][0], c[mi][ni][1]);
            *(float2*)&st[(r0 + 8) * SPITCH + cc] = make_float2(c[mi][ni][2], c[mi][ni][3]);
        }
    }
    __syncthreads();

    // ---- RoPE (pair d, d+32) + bf16 split + store ----
    const int rowp = tid >> 5;      // 0..7
    const int d    = tid & 31;      // 0..31
#pragma unroll
    for (int hs = 0; hs < 2; hs++) {
#pragma unroll
        for (int p = 0; p < 16; p++) {
            int rl = p * 8 + rowp;
            int m = bm + rl;
            int pos = m & (S_ - 1);
            float x1 = st[rl * SPITCH + hs * 64 + d];
            float x2 = st[rl * SPITCH + hs * 64 + d + 32];
            float y1, y2;
            if (dorope) {
                float cc = tab[pos * 64 + d];
                float ss = tab[pos * 64 + 32 + d];
                y1 = (x1 * cc - x2 * ss) * scale;
                y2 = (x2 * cc + x1 * ss) * scale;
            } else {
                y1 = x1; y2 = x2;
            }
            __nv_bfloat16 h1 = __float2bfloat16_rn(y1);
            __nv_bfloat16 h2 = __float2bfloat16_rn(y2);
            size_t o = (size_t)m * N + bn + hs * 64 + d;
            oh[o]      = h1;
            oh[o + 32] = h2;
            ol[o]      = __float2bfloat16_rn(y1 - __bfloat162float(h1));
            ol[o + 32] = __float2bfloat16_rn(y2 - __bfloat162float(h2));
        }
    }
}

// output projection (plain fp32 epilogue)
__global__ __launch_bounds__(256, 2) void gemm_o(
    const __nv_bfloat16* __restrict__ Ah, const __nv_bfloat16* __restrict__ Al,
    const __nv_bfloat16* __restrict__ Bh, const __nv_bfloat16* __restrict__ Bl,
    float* __restrict__ C)
{
    extern __shared__ char sm[];
    const int bm = blockIdx.y * 128;
    const int bn = blockIdx.x * 128;
    float c[4][4][4];
    gemm_mainloop(Ah, Al, Bh, Bl, H_, bm, bn, sm, c);

    const int tid  = threadIdx.x;
    const int wid  = tid >> 5;
    const int lane = tid & 31;
    const int wm = (wid & 1) * 64;
    const int wn = (wid >> 1) * 32;
    const int g  = lane >> 2;
    const int tq = lane & 3;
#pragma unroll
    for (int mi = 0; mi < 4; mi++) {
#pragma unroll
        for (int ni = 0; ni < 4; ni++) {
            int r0 = bm + wm + mi * 16 + g;
            int cc = bn + wn + ni * 8 + tq * 2;
            *(float2*)(C + (size_t)r0 * H_ + cc)       = make_float2(c[mi][ni][0], c[mi][ni][1]);
            *(float2*)(C + (size_t)(r0 + 8) * H_ + cc) = make_float2(c[mi][ni][2], c[mi][ni][3]);
        }
    }
}

// ---------------- tensor-core causal flash attention (bf16x3) --------------
// grid (S/64, HQ, B), 128 threads, 4 CTAs/SM, SINGLE-buffered KV tile.
// With 4 CTAs/SM the exposed per-CTA load latency is covered by cross-CTA
// overlap instead of per-CTA double buffering (smem 36.9 KB vs 73.7 KB).
#define APB 144                    // smem pitch bytes (72 bf16)
#define AT  (64 * APB)             // 9216 per 64x64 tile
#define ASM1 (4 * AT)              // 36864: one stage (Kh,Kl,Vh,Vl)

__global__ __launch_bounds__(128, 4) void attn_mma(
    const __nv_bfloat16* __restrict__ Qh, const __nv_bfloat16* __restrict__ Ql,
    const __nv_bfloat16* __restrict__ Kh, const __nv_bfloat16* __restrict__ Kl,
    const __nv_bfloat16* __restrict__ Vh, const __nv_bfloat16* __restrict__ Vl,
    __nv_bfloat16* __restrict__ Ch, __nv_bfloat16* __restrict__ Cl)
{
    extern __shared__ char sm[];
    const uint32_t sb = smem_u32(sm);

    const int tid  = threadIdx.x;
    const int w    = tid >> 5;
    const int lane = tid & 31;
    const int qt = blockIdx.x;
    const int h  = blockIdx.y;
    const int b  = blockIdx.z;
    const int hk = h >> 2;
    const int q0 = qt * 64;
    const int g  = lane >> 2;
    const int tq = lane & 3;

    auto load_kv = [&](int k0) {
#pragma unroll
        for (int i = 0; i < 4; i++) {
            int idx = i * 128 + tid;
            int row = idx >> 3, ch = idx & 7;
            uint32_t soff = (uint32_t)row * APB + (uint32_t)ch * 16;
            size_t goff = ((size_t)(b * S_ + k0 + row) * HK_ + hk) * 64 + ch * 8;
            asm volatile("cp.async.cg.shared.global [%0], [%1], 16;" :: "r"(sb + 0*AT + soff), "l"(Kh + goff));
            asm volatile("cp.async.cg.shared.global [%0], [%1], 16;" :: "r"(sb + 1*AT + soff), "l"(Kl + goff));
            asm volatile("cp.async.cg.shared.global [%0], [%1], 16;" :: "r"(sb + 2*AT + soff), "l"(Vh + goff));
            asm volatile("cp.async.cg.shared.global [%0], [%1], 16;" :: "r"(sb + 3*AT + soff), "l"(Vl + goff));
        }
        asm volatile("cp.async.commit_group;");
    };

    // ---- stage Q hi/lo into slots 0/1, extract frags, then recycle smem ----
#pragma unroll
    for (int i = 0; i < 4; i++) {
        int idx = i * 128 + tid;
        int row = idx >> 3, ch = idx & 7;
        uint32_t soff = (uint32_t)row * APB + (uint32_t)ch * 16;
        size_t goff = ((size_t)(b * S_ + q0 + row) * HQ_ + h) * 64 + ch * 8;
        asm volatile("cp.async.cg.shared.global [%0], [%1], 16;" :: "r"(sb + soff), "l"(Qh + goff));
        asm volatile("cp.async.cg.shared.global [%0], [%1], 16;" :: "r"(sb + AT + soff), "l"(Ql + goff));
    }
    asm volatile("cp.async.commit_group;");
    asm volatile("cp.async.wait_group 0;" ::: "memory");
    __syncthreads();

    uint32_t qa_h[4][4], qa_l[4][4];
    const uint32_t qoff = (uint32_t)(w * 16 + (lane & 15)) * APB + (uint32_t)(lane >> 4) * 16;
#pragma unroll
    for (int kc = 0; kc < 4; kc++) {
        ldm_x4(qa_h[kc], sb + qoff + kc * 32);
        ldm_x4(qa_l[kc], sb + AT + qoff + kc * 32);
    }
    __syncthreads();   // all warps done reading Q; smem free for KV

    float acc[8][4];
#pragma unroll
    for (int i = 0; i < 8; i++)
#pragma unroll
        for (int j = 0; j < 4; j++) acc[i][j] = 0.0f;
    float m0 = -1e30f, m1 = -1e30f, l0 = 0.0f, l1 = 0.0f;

    const int qrow0 = q0 + w * 16 + g;
    const uint32_t kb_off = (uint32_t)((lane & 7) + ((lane & 16) >> 1)) * APB
                          + (uint32_t)((lane >> 3) & 1) * 16;
    const uint32_t vb_row = (uint32_t)(lane & 15) * APB + (uint32_t)((lane >> 4) << 3) * 2;

    const int nkt = qt + 1;
    for (int kt = 0; kt < nkt; kt++) {
        const int k0 = kt * 64;
        // single-buffer: previous iteration's trailing sync guarantees the
        // buffer is free; load, wait, sync, compute, sync.
        load_kv(k0);
        asm volatile("cp.async.wait_group 0;" ::: "memory");
        __syncthreads();

        // ---- S = Q K^T (bf16x3) ----
        float Sv[8][4];
#pragma unroll
        for (int i = 0; i < 8; i++)
#pragma unroll
            for (int j = 0; j < 4; j++) Sv[i][j] = 0.0f;

#pragma unroll
        for (int kc = 0; kc < 4; kc++) {
#pragma unroll
            for (int p = 0; p < 4; p++) {
                uint32_t kbh[4], kbl[4];
                uint32_t ba = sb + (uint32_t)(16 * p) * APB + kb_off + kc * 32;
                ldm_x4(kbh, ba);
                ldm_x4(kbl, ba + AT);
                mma16816(Sv[2*p],   qa_h[kc], kbh[0], kbh[1]);
                mma16816(Sv[2*p],   qa_h[kc], kbl[0], kbl[1]);
                mma16816(Sv[2*p],   qa_l[kc], kbh[0], kbh[1]);
                mma16816(Sv[2*p+1], qa_h[kc], kbh[2], kbh[3]);
                mma16816(Sv[2*p+1], qa_h[kc], kbl[2], kbl[3]);
                mma16816(Sv[2*p+1], qa_l[kc], kbh[2], kbh[3]);
            }
        }

        // ---- causal mask on diagonal tile ----
        if (kt == qt) {
#pragma unroll
            for (int nt = 0; nt < 8; nt++) {
                int col = k0 + nt * 8 + tq * 2;
                if (col > qrow0)         Sv[nt][0] = -1e30f;
                if (col + 1 > qrow0)     Sv[nt][1] = -1e30f;
                if (col > qrow0 + 8)     Sv[nt][2] = -1e30f;
                if (col + 1 > qrow0 + 8) Sv[nt][3] = -1e30f;
            }
        }

        // ---- online softmax ----
        float tm0 = Sv[0][0], tm1 = Sv[0][2];
#pragma unroll
        for (int nt = 0; nt < 8; nt++) {
            tm0 = fmaxf(tm0, fmaxf(Sv[nt][0], Sv[nt][1]));
            tm1 = fmaxf(tm1, fmaxf(Sv[nt][2], Sv[nt][3]));
        }
        tm0 = fmaxf(tm0, __shfl_xor_sync(0xffffffffu, tm0, 1));
        tm0 = fmaxf(tm0, __shfl_xor_sync(0xffffffffu, tm0, 2));
        tm1 = fmaxf(tm1, __shfl_xor_sync(0xffffffffu, tm1, 1));
        tm1 = fmaxf(tm1, __shfl_xor_sync(0xffffffffu, tm1, 2));
        float mn0 = fmaxf(m0, tm0), mn1 = fmaxf(m1, tm1);
        float r0 = __expf(m0 - mn0), r1 = __expf(m1 - mn1);
        m0 = mn0; m1 = mn1;
        l0 *= r0; l1 *= r1;
#pragma unroll
        for (int dt = 0; dt < 8; dt++) {
            acc[dt][0] *= r0; acc[dt][1] *= r0;
            acc[dt][2] *= r1; acc[dt][3] *= r1;
        }
#pragma unroll
        for (int nt = 0; nt < 8; nt++) {
            Sv[nt][0] = __expf(Sv[nt][0] - m0);
            Sv[nt][1] = __expf(Sv[nt][1] - m0);
            Sv[nt][2] = __expf(Sv[nt][2] - m1);
            Sv[nt][3] = __expf(Sv[nt][3] - m1);
            l0 += Sv[nt][0] + Sv[nt][1];
            l1 += Sv[nt][2] + Sv[nt][3];
        }

        // ---- ctx += P V (bf16x3) ----
#pragma unroll
        for (int kc = 0; kc < 4; kc++) {
            uint32_t aph[4], apl[4];
            aph[0] = pack2_hi(Sv[2*kc][0],   Sv[2*kc][1]);
            aph[1] = pack2_hi(Sv[2*kc][2],   Sv[2*kc][3]);
            aph[2] = pack2_hi(Sv[2*kc+1][0], Sv[2*kc+1][1]);
            aph[3] = pack2_hi(Sv[2*kc+1][2], Sv[2*kc+1][3]);
            apl[0] = pack2_lo(Sv[2*kc][0],   Sv[2*kc][1]);
            apl[1] = pack2_lo(Sv[2*kc][2],   Sv[2*kc][3]);
            apl[2] = pack2_lo(Sv[2*kc+1][0], Sv[2*kc+1][1]);
            apl[3] = pack2_lo(Sv[2*kc+1][2], Sv[2*kc+1][3]);
#pragma unroll
            for (int dp = 0; dp < 4; dp++) {
                uint32_t vbh[4], vbl[4];
                uint32_t va = sb + 2*AT + (uint32_t)(kc * 16) * APB + (uint32_t)(dp * 32) + vb_row;
                ldm_x4_t(vbh, va);
                ldm_x4_t(vbl, va + AT);
                mma16816(acc[2*dp],   aph, vbh[0], vbh[1]);
                mma16816(acc[2*dp],   aph, vbl[0], vbl[1]);
                mma16816(acc[2*dp],   apl, vbh[0], vbh[1]);
                mma16816(acc[2*dp+1], aph, vbh[2], vbh[3]);
                mma16816(acc[2*dp+1], aph, vbl[2], vbl[3]);
                mma16816(acc[2*dp+1], apl, vbh[2], vbh[3]);
            }
        }
        __syncthreads();   // buffer free for next iteration's load
    }

    // ---- finalize ----
    l0 += __shfl_xor_sync(0xffffffffu, l0, 1);
    l0 += __shfl_xor_sync(0xffffffffu, l0, 2);
    l1 += __shfl_xor_sync(0xffffffffu, l1, 1);
    l1 += __shfl_xor_sync(0xffffffffu, l1, 2);
    float inv0 = 1.0f / l0, inv1 = 1.0f / l1;

    size_t base0 = ((size_t)(b * S_ + qrow0) * HQ_ + h) * 64;
    size_t base1 = ((size_t)(b * S_ + qrow0 + 8) * HQ_ + h) * 64;
#pragma unroll
    for (int dt = 0; dt < 8; dt++) {
        int d = dt * 8 + tq * 2;
        float a0 = acc[dt][0] * inv0, a1 = acc[dt][1] * inv0;
        float a2 = acc[dt][2] * inv1, a3 = acc[dt][3] * inv1;
        *(uint32_t*)(Ch + base0 + d) = pack2_hi(a0, a1);
        *(uint32_t*)(Cl + base0 + d) = pack2_lo(a0, a1);
        *(uint32_t*)(Ch + base1 + d) = pack2_hi(a2, a3);
        *(uint32_t*)(Cl + base1 + d) = pack2_lo(a2, a3);
    }
}

// ---------------- launch ----------------
extern "C" void kernel_launch(void* const* d_in, const int* in_sizes, int n_in,
                              void* d_out, int out_size)
{
    const float* X  = (const float*)d_in[0];
    const float* Wq = (const float*)d_in[1];
    const float* Wk = (const float*)d_in[2];
    const float* Wv = (const float*)d_in[3];
    const float* Wo = (const float*)d_in[4];
    float* out = (float*)d_out;

    float* rope;
    cudaGetSymbolAddress((void**)&rope, g_rope);

    __nv_bfloat16 *Xh, *Xl, *Wqh, *Wql, *Wkh, *Wkl, *Wvh, *Wvl, *Woh, *Wol;
    __nv_bfloat16 *qh, *ql, *kh, *kl, *vh, *vl, *Ch, *Cl;
    cudaGetSymbolAddress((void**)&Xh, g_Xh);   cudaGetSymbolAddress((void**)&Xl, g_Xl);
    cudaGetSymbolAddress((void**)&Wqh, g_Wqh); cudaGetSymbolAddress((void**)&Wql, g_Wql);
    cudaGetSymbolAddress((void**)&Wkh, g_Wkh); cudaGetSymbolAddress((void**)&Wkl, g_Wkl);
    cudaGetSymbolAddress((void**)&Wvh, g_Wvh); cudaGetSymbolAddress((void**)&Wvl, g_Wvl);
    cudaGetSymbolAddress((void**)&Woh, g_Woh); cudaGetSymbolAddress((void**)&Wol, g_Wol);
    cudaGetSymbolAddress((void**)&qh, g_qh);   cudaGetSymbolAddress((void**)&ql, g_ql);
    cudaGetSymbolAddress((void**)&kh, g_kh);   cudaGetSymbolAddress((void**)&kl, g_kl);
    cudaGetSymbolAddress((void**)&vh, g_vh);   cudaGetSymbolAddress((void**)&vl, g_vl);
    cudaGetSymbolAddress((void**)&Ch, g_Ch);   cudaGetSymbolAddress((void**)&Cl, g_Cl);

    cudaFuncSetAttribute(gemm_qkv, cudaFuncAttributeMaxDynamicSharedMemorySize, GSM2);
    cudaFuncSetAttribute(gemm_o,   cudaFuncAttributeMaxDynamicSharedMemorySize, GSM2);
    cudaFuncSetAttribute(attn_mma, cudaFuncAttributeMaxDynamicSharedMemorySize, ASM1);

    // split all 5 inputs into bf16 hi/lo (one launch, low-reg kernel)
    split_all_kernel<<<(N4_ALL + 255) / 256, 256>>>(
        X, Wq, Wk, Wv, Wo,
        Xh, Xl, Wqh, Wql, Wkh, Wkl, Wvh, Wvl, Woh, Wol);

    // RoPE table (separate: keeps split kernel's register count low)
    rope_table_kernel<<<(S_ * 32 + 255) / 256, 256>>>(rope);

    // fused QKV projection + RoPE + split (tensor cores)
    gemm_qkv<<<dim3(24, M_ / 128), 256, GSM2>>>(Xh, Xl, Wqh, Wql, Wkh, Wkl,
                                                Wvh, Wvl, rope,
                                                qh, ql, kh, kl, vh, vl);

    // tensor-core causal flash attention -> Ch/Cl (4 CTAs/SM, single-buffer)
    attn_mma<<<dim3(S_ / 64, HQ_, B_), 128, ASM1>>>(qh, ql, kh, kl, vh, vl, Ch, Cl);

    // output projection (tensor cores)
    gemm_o<<<dim3(H_ / 128, M_ / 128), 256, GSM2>>>(Ch, Cl, Woh, Wol, out);
}

// round 16
// speedup vs baseline: 1.0504x; 1.0504x over previous
#include <cuda_runtime.h>
#include <cuda_bf16.h>
#include <cstdint>
#include <math.h>

// ---------------- problem constants ----------------
#define B_   2
#define S_   2048
#define H_   2048
#define HQ_  32
#define HK_  8
#define D_   64
#define M_   (B_ * S_)        // 4096 rows

// ---------------- device scratch ----------------
__device__ float g_rope[S_ * D_];

__device__ __nv_bfloat16 g_Xh[(size_t)M_ * H_];
__device__ __nv_bfloat16 g_Xl[(size_t)M_ * H_];
__device__ __nv_bfloat16 g_Wqh[(size_t)H_ * H_];
__device__ __nv_bfloat16 g_Wql[(size_t)H_ * H_];
__device__ __nv_bfloat16 g_Wkh[(size_t)(HK_*D_) * H_];
__device__ __nv_bfloat16 g_Wkl[(size_t)(HK_*D_) * H_];
__device__ __nv_bfloat16 g_Wvh[(size_t)(HK_*D_) * H_];
__device__ __nv_bfloat16 g_Wvl[(size_t)(HK_*D_) * H_];
__device__ __nv_bfloat16 g_Woh[(size_t)H_ * H_];
__device__ __nv_bfloat16 g_Wol[(size_t)H_ * H_];

__device__ __nv_bfloat16 g_qh[(size_t)M_ * HQ_ * D_];
__device__ __nv_bfloat16 g_ql[(size_t)M_ * HQ_ * D_];
__device__ __nv_bfloat16 g_kh[(size_t)M_ * HK_ * D_];
__device__ __nv_bfloat16 g_kl[(size_t)M_ * HK_ * D_];
__device__ __nv_bfloat16 g_vh[(size_t)M_ * HK_ * D_];
__device__ __nv_bfloat16 g_vl[(size_t)M_ * HK_ * D_];
__device__ __nv_bfloat16 g_Ch[(size_t)M_ * H_];
__device__ __nv_bfloat16 g_Cl[(size_t)M_ * H_];

// ---------------- helpers ----------------
__device__ __forceinline__ uint32_t smem_u32(const void* p) {
    uint32_t a;
    asm("{ .reg .u64 t; cvta.to.shared.u64 t, %1; cvt.u32.u64 %0, t; }" : "=r"(a) : "l"(p));
    return a;
}

__device__ __forceinline__ void ldm_x4(uint32_t r[4], uint32_t addr) {
    asm volatile("ldmatrix.sync.aligned.m8n8.x4.shared.b16 {%0,%1,%2,%3}, [%4];"
        : "=r"(r[0]), "=r"(r[1]), "=r"(r[2]), "=r"(r[3]) : "r"(addr));
}
__device__ __forceinline__ void ldm_x4_t(uint32_t r[4], uint32_t addr) {
    asm volatile("ldmatrix.sync.aligned.m8n8.x4.trans.shared.b16 {%0,%1,%2,%3}, [%4];"
        : "=r"(r[0]), "=r"(r[1]), "=r"(r[2]), "=r"(r[3]) : "r"(addr));
}

__device__ __forceinline__ void mma16816(float c[4], const uint32_t a[4],
                                         uint32_t b0, uint32_t b1) {
    asm volatile(
        "mma.sync.aligned.m16n8k16.row.col.f32.bf16.bf16.f32 "
        "{%0,%1,%2,%3},{%4,%5,%6,%7},{%8,%9},{%0,%1,%2,%3};"
        : "+f"(c[0]), "+f"(c[1]), "+f"(c[2]), "+f"(c[3])
        : "r"(a[0]), "r"(a[1]), "r"(a[2]), "r"(a[3]), "r"(b0), "r"(b1));
}

__device__ __forceinline__ uint32_t pack2_hi(float a, float b) {
    __nv_bfloat162 t = __floats2bfloat162_rn(a, b);
    return *(uint32_t*)&t;
}
__device__ __forceinline__ uint32_t pack2_lo(float a, float b) {
    __nv_bfloat16 ah = __float2bfloat16_rn(a);
    __nv_bfloat16 bh = __float2bfloat16_rn(b);
    __nv_bfloat162 t = __floats2bfloat162_rn(a - __bfloat162float(ah),
                                             b - __bfloat162float(bh));
    return *(uint32_t*)&t;
}

// ---------------- fused split of all 5 inputs (fp32 -> bf16 hi/lo) ---------
#define N4_X   (M_ * H_ / 4)
#define N4_WQ  (H_ * H_ / 4)
#define N4_WK  (HK_ * D_ * H_ / 4)
#define N4_WV  (HK_ * D_ * H_ / 4)
#define N4_WO  (H_ * H_ / 4)
#define N4_ALL (N4_X + N4_WQ + N4_WK + N4_WV + N4_WO)

__global__ __launch_bounds__(256) void split_all_kernel(
    const float* __restrict__ X,  const float* __restrict__ Wq,
    const float* __restrict__ Wk, const float* __restrict__ Wv,
    const float* __restrict__ Wo,
    __nv_bfloat16* __restrict__ Xh,  __nv_bfloat16* __restrict__ Xl,
    __nv_bfloat16* __restrict__ Wqh, __nv_bfloat16* __restrict__ Wql,
    __nv_bfloat16* __restrict__ Wkh, __nv_bfloat16* __restrict__ Wkl,
    __nv_bfloat16* __restrict__ Wvh, __nv_bfloat16* __restrict__ Wvl,
    __nv_bfloat16* __restrict__ Woh, __nv_bfloat16* __restrict__ Wol)
{
    int i = blockIdx.x * blockDim.x + threadIdx.x;
    if (i >= N4_ALL) return;
    const float* in;
    __nv_bfloat16 *hi, *lo;
    if (i < N4_X)                          { in = X;  hi = Xh;  lo = Xl; }
    else if ((i -= N4_X)  < N4_WQ)         { in = Wq; hi = Wqh; lo = Wql; }
    else if ((i -= N4_WQ) < N4_WK)         { in = Wk; hi = Wkh; lo = Wkl; }
    else if ((i -= N4_WK) < N4_WV)         { in = Wv; hi = Wvh; lo = Wvl; }
    else      { i -= N4_WV;                  in = Wo; hi = Woh; lo = Wol; }

    float4 x = *(const float4*)(in + (size_t)i * 4);
    __nv_bfloat16 h[4], l[4];
    float xs[4] = {x.x, x.y, x.z, x.w};
#pragma unroll
    for (int j = 0; j < 4; j++) {
        h[j] = __float2bfloat16_rn(xs[j]);
        l[j] = __float2bfloat16_rn(xs[j] - __bfloat162float(h[j]));
    }
    *(uint2*)(hi + (size_t)i * 4) = *(uint2*)h;
    *(uint2*)(lo + (size_t)i * 4) = *(uint2*)l;
}

// ---------------- RoPE table (float, matches reference's float path) -------
__global__ void rope_table_kernel(float* __restrict__ tab)
{
    int idx = blockIdx.x * blockDim.x + threadIdx.x;
    if (idx >= S_ * 32) return;
    int half = idx & 31;
    int pos  = idx >> 5;
    // inv_freq = 10000^(-2*half/64), computed in float like the reference
    float inv = exp2f(-((float)(2 * half) / 64.0f) * log2f(10000.0f));
    float ang = (float)pos * inv;
    float s, c;
    sincosf(ang, &s, &c);
    tab[pos * 64 + half]      = c;
    tab[pos * 64 + 32 + half] = s;
}

// ---------------- bf16x3 GEMM mainloop: BK=32, 2 stages, 1 sync/chunk ------
// 128x128 block tile, 256 threads (8 warps, 2x4), warp tile 64x32.
// R9-proven structure. 80 KB smem + <=128 regs -> 2 CTAs/SM (load-bearing).
#define GP2   80
#define TIL2  (128 * GP2)          // 10240
#define STG2  (4 * TIL2)           // 40960
#define GSM2  (2 * STG2)           // 81920

__device__ __forceinline__ void gemm_mainloop(
    const __nv_bfloat16* __restrict__ Ah, const __nv_bfloat16* __restrict__ Al,
    const __nv_bfloat16* __restrict__ Bh, const __nv_bfloat16* __restrict__ Bl,
    int K, int bm, int bn, char* smp, float c[4][4][4])
{
    const uint32_t sb = smem_u32(smp);
    const int tid  = threadIdx.x;
    const int wid  = tid >> 5;
    const int lane = tid & 31;
    const int wm = (wid & 1) * 64;
    const int wn = (wid >> 1) * 32;

    const __nv_bfloat16* gp[4] = {
        Ah + (size_t)bm * K, Al + (size_t)bm * K,
        Bh + (size_t)bn * K, Bl + (size_t)bn * K };

    const uint32_t a_off = (uint32_t)(lane & 15) * GP2 + (uint32_t)(lane >> 4) * 16;
    const uint32_t b_off = (uint32_t)((lane & 7) + ((lane & 16) >> 1)) * GP2
                         + (uint32_t)((lane >> 3) & 1) * 16;

#pragma unroll
    for (int i = 0; i < 4; i++)
#pragma unroll
        for (int j = 0; j < 4; j++)
#pragma unroll
            for (int q = 0; q < 4; q++) c[i][j][q] = 0.0f;

    const int nc = K >> 5;

    auto load_stage = [&](int stage, int k0) {
        const uint32_t sbase = sb + (uint32_t)stage * STG2;
#pragma unroll
        for (int rep = 0; rep < 2; rep++) {
            int idx = rep * 256 + tid;
            int row = idx >> 2, ch = idx & 3;
            uint32_t so = (uint32_t)row * GP2 + (uint32_t)ch * 16;
#pragma unroll
            for (int t = 0; t < 4; t++) {
                const void* src = gp[t] + (size_t)row * K + k0 + ch * 8;
                asm volatile("cp.async.cg.shared.global [%0], [%1], 16;"
                    :: "r"(sbase + (uint32_t)t * TIL2 + so), "l"(src));
            }
        }
        asm volatile("cp.async.commit_group;");
    };

    load_stage(0, 0);

    for (int cidx = 0; cidx < nc; cidx++) {
        asm volatile("cp.async.wait_group 0;" ::: "memory");
        __syncthreads();
        if (cidx + 1 < nc) load_stage((cidx + 1) & 1, (cidx + 1) << 5);

        const uint32_t st = sb + (uint32_t)(cidx & 1) * STG2;
        const uint32_t baseAh = st + 0 * TIL2;
        const uint32_t baseAl = st + 1 * TIL2;
        const uint32_t baseBh = st + 2 * TIL2;
        const uint32_t baseBl = st + 3 * TIL2;

#pragma unroll
        for (int kc = 0; kc < 2; kc++) {
            uint32_t ah[4][4], al[4][4], bh[2][4], bl[2][4];
#pragma unroll
            for (int mt = 0; mt < 4; mt++) {
                uint32_t ro = (uint32_t)(wm + mt * 16) * GP2 + kc * 32;
                ldm_x4(ah[mt], baseAh + ro + a_off);
                ldm_x4(al[mt], baseAl + ro + a_off);
            }
#pragma unroll
            for (int nt = 0; nt < 2; nt++) {
                uint32_t ro = (uint32_t)(wn + nt * 16) * GP2 + kc * 32;
                ldm_x4(bh[nt], baseBh + ro + b_off);
                ldm_x4(bl[nt], baseBl + ro + b_off);
            }
#pragma unroll
            for (int mi = 0; mi < 4; mi++) {
#pragma unroll
                for (int ni = 0; ni < 4; ni++) {
                    const int nt = ni >> 1, hf = (ni & 1) * 2;
                    mma16816(c[mi][ni], ah[mi], bh[nt][hf], bh[nt][hf + 1]);
                    mma16816(c[mi][ni], ah[mi], bl[nt][hf], bl[nt][hf + 1]);
                    mma16816(c[mi][ni], al[mi], bh[nt][hf], bh[nt][hf + 1]);
                }
            }
        }
    }
}

// fused QKV projection + RoPE + bf16 hi/lo split.
// blockIdx.x 0..15 -> Q, 16..19 -> K, 20..23 -> V
#define SPITCH 132   // fp32 staging pitch (floats)

__global__ __launch_bounds__(256, 2) void gemm_qkv(
    const __nv_bfloat16* __restrict__ Xh, const __nv_bfloat16* __restrict__ Xl,
    const __nv_bfloat16* __restrict__ Wqh, const __nv_bfloat16* __restrict__ Wql,
    const __nv_bfloat16* __restrict__ Wkh, const __nv_bfloat16* __restrict__ Wkl,
    const __nv_bfloat16* __restrict__ Wvh, const __nv_bfloat16* __restrict__ Wvl,
    const float* __restrict__ tab,
    __nv_bfloat16* __restrict__ qh, __nv_bfloat16* __restrict__ ql,
    __nv_bfloat16* __restrict__ kh, __nv_bfloat16* __restrict__ kl,
    __nv_bfloat16* __restrict__ vh, __nv_bfloat16* __restrict__ vl)
{
    extern __shared__ char sm[];
    const int nb = blockIdx.x;
    const int bm = blockIdx.y * 128;

    const __nv_bfloat16 *Bh, *Bl;
    __nv_bfloat16 *oh, *ol;
    int N, bn;
    bool dorope;
    float scale;
    if (nb < 16)      { Bh = Wqh; Bl = Wql; oh = qh; ol = ql; N = HQ_ * D_; bn = nb * 128;        dorope = true;  scale = 0.125f; }
    else if (nb < 20) { Bh = Wkh; Bl = Wkl; oh = kh; ol = kl; N = HK_ * D_; bn = (nb - 16) * 128; dorope = true;  scale = 1.0f; }
    else              { Bh = Wvh; Bl = Wvl; oh = vh; ol = vl; N = HK_ * D_; bn = (nb - 20) * 128; dorope = false; scale = 1.0f; }

    float c[4][4][4];
    gemm_mainloop(Xh, Xl, Bh, Bl, H_, bm, bn, sm, c);

    // ---- stage fp32 tile in smem ----
    float* st = (float*)sm;
    const int tid  = threadIdx.x;
    const int wid  = tid >> 5;
    const int lane = tid & 31;
    const int wm = (wid & 1) * 64;
    const int wn = (wid >> 1) * 32;
    const int g  = lane >> 2;
    const int tq = lane & 3;

    __syncthreads();
#pragma unroll
    for (int mi = 0; mi < 4; mi++) {
#pragma unroll
        for (int ni = 0; ni < 4; ni++) {
            int r0 = wm + mi * 16 + g;
            int cc = wn + ni * 8 + tq * 2;
            *(float2*)&st[r0 * SPITCH + cc]       = make_float2(c[mi][ni][0], c[mi][ni][1]);
            *(float2*)&st[(r0 + 8) * SPITCH + cc] = make_float2(c[mi][ni][2], c[mi][ni][3]);
        }
    }
    __syncthreads();

    // ---- RoPE (pair d, d+32) + bf16 split + store ----
    const int rowp = tid >> 5;      // 0..7
    const int d    = tid & 31;      // 0..31
#pragma unroll
    for (int hs = 0; hs < 2; hs++) {
#pragma unroll
        for (int p = 0; p < 16; p++) {
            int rl = p * 8 + rowp;
            int m = bm + rl;
            int pos = m & (S_ - 1);
            float x1 = st[rl * SPITCH + hs * 64 + d];
            float x2 = st[rl * SPITCH + hs * 64 + d + 32];
            float y1, y2;
            if (dorope) {
                float cc = tab[pos * 64 + d];
                float ss = tab[pos * 64 + 32 + d];
                y1 = (x1 * cc - x2 * ss) * scale;
                y2 = (x2 * cc + x1 * ss) * scale;
            } else {
                y1 = x1; y2 = x2;
            }
            __nv_bfloat16 h1 = __float2bfloat16_rn(y1);
            __nv_bfloat16 h2 = __float2bfloat16_rn(y2);
            size_t o = (size_t)m * N + bn + hs * 64 + d;
            oh[o]      = h1;
            oh[o + 32] = h2;
            ol[o]      = __float2bfloat16_rn(y1 - __bfloat162float(h1));
            ol[o + 32] = __float2bfloat16_rn(y2 - __bfloat162float(h2));
        }
    }
}

// output projection (plain fp32 epilogue)
__global__ __launch_bounds__(256, 2) void gemm_o(
    const __nv_bfloat16* __restrict__ Ah, const __nv_bfloat16* __restrict__ Al,
    const __nv_bfloat16* __restrict__ Bh, const __nv_bfloat16* __restrict__ Bl,
    float* __restrict__ C)
{
    extern __shared__ char sm[];
    const int bm = blockIdx.y * 128;
    const int bn = blockIdx.x * 128;
    float c[4][4][4];
    gemm_mainloop(Ah, Al, Bh, Bl, H_, bm, bn, sm, c);

    const int tid  = threadIdx.x;
    const int wid  = tid >> 5;
    const int lane = tid & 31;
    const int wm = (wid & 1) * 64;
    const int wn = (wid >> 1) * 32;
    const int g  = lane >> 2;
    const int tq = lane & 3;
#pragma unroll
    for (int mi = 0; mi < 4; mi++) {
#pragma unroll
        for (int ni = 0; ni < 4; ni++) {
            int r0 = bm + wm + mi * 16 + g;
            int cc = bn + wn + ni * 8 + tq * 2;
            *(float2*)(C + (size_t)r0 * H_ + cc)       = make_float2(c[mi][ni][0], c[mi][ni][1]);
            *(float2*)(C + (size_t)(r0 + 8) * H_ + cc) = make_float2(c[mi][ni][2], c[mi][ni][3]);
        }
    }
}

// ---------------- tensor-core causal flash attention (bf16x3) --------------
// grid (S/64, HQ, B), 128 threads, 3 CTAs/SM. Double-buffered K/V tiles.
// R14-proven structure (single-sync pipeline).
#define APB 144                    // smem pitch bytes (72 bf16)
#define AT  (64 * APB)             // 9216 per 64x64 tile
#define ASM (8 * AT)               // 73728: 2 stages x (Kh,Kl,Vh,Vl)

__global__ __launch_bounds__(128, 3) void attn_mma(
    const __nv_bfloat16* __restrict__ Qh, const __nv_bfloat16* __restrict__ Ql,
    const __nv_bfloat16* __restrict__ Kh, const __nv_bfloat16* __restrict__ Kl,
    const __nv_bfloat16* __restrict__ Vh, const __nv_bfloat16* __restrict__ Vl,
    __nv_bfloat16* __restrict__ Ch, __nv_bfloat16* __restrict__ Cl)
{
    extern __shared__ char sm[];
    const uint32_t sb = smem_u32(sm);

    const int tid  = threadIdx.x;
    const int w    = tid >> 5;
    const int lane = tid & 31;
    const int qt = blockIdx.x;
    const int h  = blockIdx.y;
    const int b  = blockIdx.z;
    const int hk = h >> 2;
    const int q0 = qt * 64;
    const int g  = lane >> 2;
    const int tq = lane & 3;

    auto load_kv = [&](int buf, int k0) {
        const uint32_t base = sb + (uint32_t)buf * (4 * AT);
#pragma unroll
        for (int i = 0; i < 4; i++) {
            int idx = i * 128 + tid;
            int row = idx >> 3, ch = idx & 7;
            uint32_t soff = (uint32_t)row * APB + (uint32_t)ch * 16;
            size_t goff = ((size_t)(b * S_ + k0 + row) * HK_ + hk) * 64 + ch * 8;
            asm volatile("cp.async.cg.shared.global [%0], [%1], 16;" :: "r"(base + 0*AT + soff), "l"(Kh + goff));
            asm volatile("cp.async.cg.shared.global [%0], [%1], 16;" :: "r"(base + 1*AT + soff), "l"(Kl + goff));
            asm volatile("cp.async.cg.shared.global [%0], [%1], 16;" :: "r"(base + 2*AT + soff), "l"(Vh + goff));
            asm volatile("cp.async.cg.shared.global [%0], [%1], 16;" :: "r"(base + 3*AT + soff), "l"(Vl + goff));
        }
        asm volatile("cp.async.commit_group;");
    };

    // ---- stage Q hi/lo into buf0 slots 0/1; KV(0) into buf1 ----
#pragma unroll
    for (int i = 0; i < 4; i++) {
        int idx = i * 128 + tid;
        int row = idx >> 3, ch = idx & 7;
        uint32_t soff = (uint32_t)row * APB + (uint32_t)ch * 16;
        size_t goff = ((size_t)(b * S_ + q0 + row) * HQ_ + h) * 64 + ch * 8;
        asm volatile("cp.async.cg.shared.global [%0], [%1], 16;" :: "r"(sb + soff), "l"(Qh + goff));
        asm volatile("cp.async.cg.shared.global [%0], [%1], 16;" :: "r"(sb + AT + soff), "l"(Ql + goff));
    }
    asm volatile("cp.async.commit_group;");
    load_kv(1, 0);
    asm volatile("cp.async.wait_group 1;" ::: "memory");   // Q ready, KV0 in flight
    __syncthreads();

    uint32_t qa_h[4][4], qa_l[4][4];
    const uint32_t qoff = (uint32_t)(w * 16 + (lane & 15)) * APB + (uint32_t)(lane >> 4) * 16;
#pragma unroll
    for (int kc = 0; kc < 4; kc++) {
        ldm_x4(qa_h[kc], sb + qoff + kc * 32);
        ldm_x4(qa_l[kc], sb + AT + qoff + kc * 32);
    }
    // buf0 (Q area) is never reused for KV; no extra sync needed.

    float acc[8][4];
#pragma unroll
    for (int i = 0; i < 8; i++)
#pragma unroll
        for (int j = 0; j < 4; j++) acc[i][j] = 0.0f;
    float m0 = -1e30f, m1 = -1e30f, l0 = 0.0f, l1 = 0.0f;

    const int qrow0 = q0 + w * 16 + g;
    const uint32_t kb_off = (uint32_t)((lane & 7) + ((lane & 16) >> 1)) * APB
                          + (uint32_t)((lane >> 3) & 1) * 16;
    const uint32_t vb_row = (uint32_t)(lane & 15) * APB + (uint32_t)((lane >> 4) << 3) * 2;

    const int nkt = qt + 1;
    for (int kt = 0; kt < nkt; kt++) {
        const int k0 = kt * 64;
        // Single-sync double buffer: wait for KV(kt), barrier (also releases
        // the buffer the upcoming prefetch overwrites), then prefetch KV(kt+1).
        asm volatile("cp.async.wait_group 0;" ::: "memory");
        __syncthreads();
        if (kt + 1 < nkt) load_kv(kt & 1, (kt + 1) * 64);

        const uint32_t kvb = sb + (uint32_t)((kt + 1) & 1) * (4 * AT);

        // ---- S = Q K^T (bf16x3) ----
        float Sv[8][4];
#pragma unroll
        for (int i = 0; i < 8; i++)
#pragma unroll
            for (int j = 0; j < 4; j++) Sv[i][j] = 0.0f;

#pragma unroll
        for (int kc = 0; kc < 4; kc++) {
#pragma unroll
            for (int p = 0; p < 4; p++) {
                uint32_t kbh[4], kbl[4];
                uint32_t ba = kvb + (uint32_t)(16 * p) * APB + kb_off + kc * 32;
                ldm_x4(kbh, ba);
                ldm_x4(kbl, ba + AT);
                mma16816(Sv[2*p],   qa_h[kc], kbh[0], kbh[1]);
                mma16816(Sv[2*p],   qa_h[kc], kbl[0], kbl[1]);
                mma16816(Sv[2*p],   qa_l[kc], kbh[0], kbh[1]);
                mma16816(Sv[2*p+1], qa_h[kc], kbh[2], kbh[3]);
                mma16816(Sv[2*p+1], qa_h[kc], kbl[2], kbl[3]);
                mma16816(Sv[2*p+1], qa_l[kc], kbh[2], kbh[3]);
            }
        }

        // ---- causal mask on diagonal tile ----
        if (kt == qt) {
#pragma unroll
            for (int nt = 0; nt < 8; nt++) {
                int col = k0 + nt * 8 + tq * 2;
                if (col > qrow0)         Sv[nt][0] = -1e30f;
                if (col + 1 > qrow0)     Sv[nt][1] = -1e30f;
                if (col > qrow0 + 8)     Sv[nt][2] = -1e30f;
                if (col + 1 > qrow0 + 8) Sv[nt][3] = -1e30f;
            }
        }

        // ---- online softmax ----
        float tm0 = Sv[0][0], tm1 = Sv[0][2];
#pragma unroll
        for (int nt = 0; nt < 8; nt++) {
            tm0 = fmaxf(tm0, fmaxf(Sv[nt][0], Sv[nt][1]));
            tm1 = fmaxf(tm1, fmaxf(Sv[nt][2], Sv[nt][3]));
        }
        tm0 = fmaxf(tm0, __shfl_xor_sync(0xffffffffu, tm0, 1));
        tm0 = fmaxf(tm0, __shfl_xor_sync(0xffffffffu, tm0, 2));
        tm1 = fmaxf(tm1, __shfl_xor_sync(0xffffffffu, tm1, 1));
        tm1 = fmaxf(tm1, __shfl_xor_sync(0xffffffffu, tm1, 2));
        float mn0 = fmaxf(m0, tm0), mn1 = fmaxf(m1, tm1);
        float r0 = __expf(m0 - mn0), r1 = __expf(m1 - mn1);
        m0 = mn0; m1 = mn1;
        l0 *= r0; l1 *= r1;
#pragma unroll
        for (int dt = 0; dt < 8; dt++) {
            acc[dt][0] *= r0; acc[dt][1] *= r0;
            acc[dt][2] *= r1; acc[dt][3] *= r1;
        }
#pragma unroll
        for (int nt = 0; nt < 8; nt++) {
            Sv[nt][0] = __expf(Sv[nt][0] - m0);
            Sv[nt][1] = __expf(Sv[nt][1] - m0);
            Sv[nt][2] = __expf(Sv[nt][2] - m1);
            Sv[nt][3] = __expf(Sv[nt][3] - m1);
            l0 += Sv[nt][0] + Sv[nt][1];
            l1 += Sv[nt][2] + Sv[nt][3];
        }

        // ---- ctx += P V (bf16x3) ----
#pragma unroll
        for (int kc = 0; kc < 4; kc++) {
            uint32_t aph[4], apl[4];
            aph[0] = pack2_hi(Sv[2*kc][0],   Sv[2*kc][1]);
            aph[1] = pack2_hi(Sv[2*kc][2],   Sv[2*kc][3]);
            aph[2] = pack2_hi(Sv[2*kc+1][0], Sv[2*kc+1][1]);
            aph[3] = pack2_hi(Sv[2*kc+1][2], Sv[2*kc+1][3]);
            apl[0] = pack2_lo(Sv[2*kc][0],   Sv[2*kc][1]);
            apl[1] = pack2_lo(Sv[2*kc][2],   Sv[2*kc][3]);
            apl[2] = pack2_lo(Sv[2*kc+1][0], Sv[2*kc+1][1]);
            apl[3] = pack2_lo(Sv[2*kc+1][2], Sv[2*kc+1][3]);
#pragma unroll
            for (int dp = 0; dp < 4; dp++) {
                uint32_t vbh[4], vbl[4];
                uint32_t va = kvb + 2*AT + (uint32_t)(kc * 16) * APB + (uint32_t)(dp * 32) + vb_row;
                ldm_x4_t(vbh, va);
                ldm_x4_t(vbl, va + AT);
                mma16816(acc[2*dp],   aph, vbh[0], vbh[1]);
                mma16816(acc[2*dp],   aph, vbl[0], vbl[1]);
                mma16816(acc[2*dp],   apl, vbh[0], vbh[1]);
                mma16816(acc[2*dp+1], aph, vbh[2], vbh[3]);
                mma16816(acc[2*dp+1], aph, vbl[2], vbl[3]);
                mma16816(acc[2*dp+1], apl, vbh[2], vbh[3]);
            }
        }
        // no end-of-loop sync: the top-of-next-iteration sync protects the
        // buffer that iteration kt+1's prefetch overwrites.
    }

    // ---- finalize ----
    l0 += __shfl_xor_sync(0xffffffffu, l0, 1);
    l0 += __shfl_xor_sync(0xffffffffu, l0, 2);
    l1 += __shfl_xor_sync(0xffffffffu, l1, 1);
    l1 += __shfl_xor_sync(0xffffffffu, l1, 2);
    float inv0 = 1.0f / l0, inv1 = 1.0f / l1;

    size_t base0 = ((size_t)(b * S_ + qrow0) * HQ_ + h) * 64;
    size_t base1 = ((size_t)(b * S_ + qrow0 + 8) * HQ_ + h) * 64;
#pragma unroll
    for (int dt = 0; dt < 8; dt++) {
        int d = dt * 8 + tq * 2;
        float a0 = acc[dt][0] * inv0, a1 = acc[dt][1] * inv0;
        float a2 = acc[dt][2] * inv1, a3 = acc[dt][3] * inv1;
        *(uint32_t*)(Ch + base0 + d) = pack2_hi(a0, a1);
        *(uint32_t*)(Cl + base0 + d) = pack2_lo(a0, a1);
        *(uint32_t*)(Ch + base1 + d) = pack2_hi(a2, a3);
        *(uint32_t*)(Cl + base1 + d) = pack2_lo(a2, a3);
    }
}

// ---------------- launch ----------------
extern "C" void kernel_launch(void* const* d_in, const int* in_sizes, int n_in,
                              void* d_out, int out_size)
{
    const float* X  = (const float*)d_in[0];
    const float* Wq = (const float*)d_in[1];
    const float* Wk = (const float*)d_in[2];
    const float* Wv = (const float*)d_in[3];
    const float* Wo = (const float*)d_in[4];
    float* out = (float*)d_out;

    float* rope;
    cudaGetSymbolAddress((void**)&rope, g_rope);

    __nv_bfloat16 *Xh, *Xl, *Wqh, *Wql, *Wkh, *Wkl, *Wvh, *Wvl, *Woh, *Wol;
    __nv_bfloat16 *qh, *ql, *kh, *kl, *vh, *vl, *Ch, *Cl;
    cudaGetSymbolAddress((void**)&Xh, g_Xh);   cudaGetSymbolAddress((void**)&Xl, g_Xl);
    cudaGetSymbolAddress((void**)&Wqh, g_Wqh); cudaGetSymbolAddress((void**)&Wql, g_Wql);
    cudaGetSymbolAddress((void**)&Wkh, g_Wkh); cudaGetSymbolAddress((void**)&Wkl, g_Wkl);
    cudaGetSymbolAddress((void**)&Wvh, g_Wvh); cudaGetSymbolAddress((void**)&Wvl, g_Wvl);
    cudaGetSymbolAddress((void**)&Woh, g_Woh); cudaGetSymbolAddress((void**)&Wol, g_Wol);
    cudaGetSymbolAddress((void**)&qh, g_qh);   cudaGetSymbolAddress((void**)&ql, g_ql);
    cudaGetSymbolAddress((void**)&kh, g_kh);   cudaGetSymbolAddress((void**)&kl, g_kl);
    cudaGetSymbolAddress((void**)&vh, g_vh);   cudaGetSymbolAddress((void**)&vl, g_vl);
    cudaGetSymbolAddress((void**)&Ch, g_Ch);   cudaGetSymbolAddress((void**)&Cl, g_Cl);

    cudaFuncSetAttribute(gemm_qkv, cudaFuncAttributeMaxDynamicSharedMemorySize, GSM2);
    cudaFuncSetAttribute(gemm_o,   cudaFuncAttributeMaxDynamicSharedMemorySize, GSM2);
    cudaFuncSetAttribute(attn_mma, cudaFuncAttributeMaxDynamicSharedMemorySize, ASM);

    // split all 5 inputs into bf16 hi/lo (one launch, low-reg kernel)
    split_all_kernel<<<(N4_ALL + 255) / 256, 256>>>(
        X, Wq, Wk, Wv, Wo,
        Xh, Xl, Wqh, Wql, Wkh, Wkl, Wvh, Wvl, Woh, Wol);

    // RoPE table (float path, matches reference's float32 trig)
    rope_table_kernel<<<(S_ * 32 + 255) / 256, 256>>>(rope);

    // fused QKV projection + RoPE + split (tensor cores)
    gemm_qkv<<<dim3(24, M_ / 128), 256, GSM2>>>(Xh, Xl, Wqh, Wql, Wkh, Wkl,
                                                Wvh, Wvl, rope,
                                                qh, ql, kh, kl, vh, vl);

    // tensor-core causal flash attention -> Ch/Cl (R14 double-buffered form)
    attn_mma<<<dim3(S_ / 64, HQ_, B_), 128, ASM>>>(qh, ql, kh, kl, vh, vl, Ch, Cl);

    // output projection (tensor cores)
    gemm_o<<<dim3(H_ / 128, M_ / 128), 256, GSM2>>>(Ch, Cl, Woh, Wol, out);
}